// round 2
// baseline (speedup 1.0000x reference)
#include <cuda_runtime.h>
#include <cuda_bf16.h>

// Problem constants (from reference):
//   B=100, C2=128, H2=64  -> c2 [100,128,64,64], pixel (7,7) => offset 455
//   B=100, C3=256, H3=32  -> c3 [100,256,32,32], pixel (3,3) => offset 99
// out = sum(((c2[:,:,7,7] > med1) - mask1)^2) + sum(((c3[:,:,3,3] > med2) - mask2)^2)

#define B_   100
#define C2_  128
#define C3_  256
#define N1_  (B_ * C2_)          // 12800
#define N2_  (B_ * C3_)          // 25600
#define NT_  (N1_ + N2_)         // 38400
#define STRIDE1_ (64 * 64)
#define PIX1_    (7 * 64 + 7)
#define STRIDE2_ (32 * 32)
#define PIX2_    (3 * 32 + 3)

#define THREADS_ 256
#define BLOCKS_  ((NT_ + THREADS_ - 1) / THREADS_)   // 150

// Scratch for single-kernel grid reduction (no cudaMalloc allowed).
__device__ float g_partials[BLOCKS_];
__device__ unsigned int g_ticket = 0;   // resets to 0 at end of every launch

__global__ void dsverifier_kernel(const float* __restrict__ c2,
                                  const float* __restrict__ c3,
                                  const float* __restrict__ mask1,
                                  const float* __restrict__ mask2,
                                  const float* __restrict__ median1,
                                  const float* __restrict__ median2,
                                  float* __restrict__ out)
{
    const float m1 = *median1;
    const float m2 = *median2;

    const int i = blockIdx.x * THREADS_ + threadIdx.x;

    float acc = 0.0f;
    if (i < N1_) {
        float v  = __ldg(&c2[(long long)i * STRIDE1_ + PIX1_]);
        float tm = (v > m1) ? 1.0f : 0.0f;
        float d  = tm - __ldg(&mask1[i]);
        acc = d * d;
    } else if (i < NT_) {
        int j = i - N1_;
        float v  = __ldg(&c3[(long long)j * STRIDE2_ + PIX2_]);
        float tm = (v > m2) ? 1.0f : 0.0f;
        float d  = tm - __ldg(&mask2[j]);
        acc = d * d;
    }

    // warp reduce
    #pragma unroll
    for (int off = 16; off > 0; off >>= 1)
        acc += __shfl_down_sync(0xFFFFFFFFu, acc, off);

    __shared__ float warp_sums[THREADS_ / 32];
    const int lane = threadIdx.x & 31;
    const int wid  = threadIdx.x >> 5;
    if (lane == 0) warp_sums[wid] = acc;
    __syncthreads();

    __shared__ bool s_is_last;
    if (wid == 0) {
        float v = (lane < (THREADS_ / 32)) ? warp_sums[lane] : 0.0f;
        #pragma unroll
        for (int off = 4; off > 0; off >>= 1)
            v += __shfl_down_sync(0xFFFFFFFFu, v, off);
        if (lane == 0) {
            g_partials[blockIdx.x] = v;
            __threadfence();                        // make partial visible
            unsigned int t = atomicAdd(&g_ticket, 1u);
            s_is_last = (t == (unsigned int)(BLOCKS_ - 1));
        }
    }
    __syncthreads();

    // Last block to arrive sums all partials and writes the result.
    if (s_is_last) {
        float v = 0.0f;
        for (int b = threadIdx.x; b < BLOCKS_; b += THREADS_) {
            // volatile read: partials were published by other blocks
            v += ((volatile float*)g_partials)[b];
        }
        #pragma unroll
        for (int off = 16; off > 0; off >>= 1)
            v += __shfl_down_sync(0xFFFFFFFFu, v, off);
        if (lane == 0) warp_sums[wid] = v;
        __syncthreads();
        if (wid == 0) {
            float s = (lane < (THREADS_ / 32)) ? warp_sums[lane] : 0.0f;
            #pragma unroll
            for (int off = 4; off > 0; off >>= 1)
                s += __shfl_down_sync(0xFFFFFFFFu, s, off);
            if (lane == 0) {
                *out = s;
                g_ticket = 0;           // reset for next graph replay
                __threadfence();
            }
        }
    }
}

extern "C" void kernel_launch(void* const* d_in, const int* in_sizes, int n_in,
                              void* d_out, int out_size)
{
    const float* c2      = (const float*)d_in[0];
    const float* c3      = (const float*)d_in[1];
    const float* mask1   = (const float*)d_in[2];
    const float* mask2   = (const float*)d_in[3];
    const float* median1 = (const float*)d_in[4];
    const float* median2 = (const float*)d_in[5];
    float* out = (float*)d_out;

    dsverifier_kernel<<<BLOCKS_, THREADS_>>>(c2, c3, mask1, mask2,
                                             median1, median2, out);
}

// round 3
// speedup vs baseline: 1.3023x; 1.3023x over previous
#include <cuda_runtime.h>
#include <cuda_bf16.h>

// Problem constants:
//   c2 [100,128,64,64] f32 -> pixel (7,7) => elem offset 7*64+7 = 455, stride 4096
//   c3 [100,256,32,32] f32 -> pixel (3,3) => elem offset 3*32+3 = 99,  stride 1024
// out = sum(((c2[:,:,7,7] > med1) != mask1)) + sum(((c3[:,:,3,3] > med2) != mask2))
// (squared diff of {0,1} values == inequality count; exact in integers)

#define B_   100
#define C2_  128
#define C3_  256
#define N1_  (B_ * C2_)          // 12800 = 50 blocks * 256
#define NT_  (N1_ + B_ * C3_)    // 38400 = 150 blocks * 256 (exact)
#define THREADS_ 256
#define BLOCKS_  (NT_ / THREADS_)        // 150
#define BLOCKS1_ (N1_ / THREADS_)        // 50

__device__ unsigned int g_sum    = 0;   // integer mismatch count (exact)
__device__ unsigned int g_ticket = 0;   // both self-reset every launch

__global__ void __launch_bounds__(THREADS_, 1)
dsverifier_kernel(const float* __restrict__ c2,
                  const float* __restrict__ c3,
                  const float* __restrict__ mask1,
                  const float* __restrict__ mask2,
                  const float* __restrict__ median1,
                  const float* __restrict__ median2,
                  float* __restrict__ out)
{
    const int tid = threadIdx.x;
    const int bid = blockIdx.x;
    const int i   = bid * THREADS_ + tid;

    bool diff;
    if (bid < BLOCKS1_) {
        // c2 path: gather pixel (7,7), compare vs median1, xor with mask1
        float v  = __ldg(&c2[(size_t)i * 4096 + 455]);
        float mk = __ldg(&mask1[i]);
        float md = __ldg(median1);
        diff = (v > md) != (mk != 0.0f);
    } else {
        const int j = i - N1_;
        float v  = __ldg(&c3[(size_t)j * 1024 + 99]);
        float mk = __ldg(&mask2[j]);
        float md = __ldg(median2);
        diff = (v > md) != (mk != 0.0f);
    }

    // warp reduce: one ballot + popc (summand is 0/1)
    const unsigned bal = __ballot_sync(0xFFFFFFFFu, diff);

    __shared__ int wsum[THREADS_ / 32];
    const int lane = tid & 31;
    const int wid  = tid >> 5;
    if (lane == 0) wsum[wid] = __popc(bal);
    __syncthreads();

    if (tid == 0) {
        int s = 0;
        #pragma unroll
        for (int w = 0; w < THREADS_ / 32; w++) s += wsum[w];

        atomicAdd(&g_sum, (unsigned)s);     // publish block count
        __threadfence();                    // order g_sum add before ticket add
        unsigned t = atomicAdd(&g_ticket, 1u);
        if (t == (unsigned)(BLOCKS_ - 1)) {
            // last block: all 150 adds reached L2 (fenced before their tickets)
            unsigned total = atomicExch(&g_sum, 0u);   // read + reset in one RMW
            *out = (float)total;                       // exact (<= 38400 < 2^24)
            atomicExch(&g_ticket, 0u);                 // reset for next replay
        }
    }
}

extern "C" void kernel_launch(void* const* d_in, const int* in_sizes, int n_in,
                              void* d_out, int out_size)
{
    const float* c2      = (const float*)d_in[0];
    const float* c3      = (const float*)d_in[1];
    const float* mask1   = (const float*)d_in[2];
    const float* mask2   = (const float*)d_in[3];
    const float* median1 = (const float*)d_in[4];
    const float* median2 = (const float*)d_in[5];
    float* out = (float*)d_out;

    dsverifier_kernel<<<BLOCKS_, THREADS_>>>(c2, c3, mask1, mask2,
                                             median1, median2, out);
}

// round 4
// speedup vs baseline: 1.3462x; 1.0337x over previous
#include <cuda_runtime.h>
#include <cuda_bf16.h>

// c2 [100,128,64,64] f32 -> pixel (7,7) => elem offset 455, channel stride 4096
// c3 [100,256,32,32] f32 -> pixel (3,3) => elem offset 99,  channel stride 1024
// out = #{ (c2[:,:,7,7] > med1) != mask1 } + #{ (c3[:,:,3,3] > med2) != mask2 }
// (squared diff of {0,1} values == mismatch count; exact integer)

#define B_   100
#define N1_  (B_ * 128)              // 12800 = 50 blocks * 256
#define NT_  (N1_ + B_ * 256)        // 38400 = 150 blocks * 256 (exact)
#define THREADS_ 256
#define BLOCKS_  (NT_ / THREADS_)    // 150
#define BLOCKS1_ (N1_ / THREADS_)    // 50
#define NWARPS_  (NT_ / 32)          // 1200 total warps

// Packed accumulator: high 32 bits = warp ticket count, low 32 = mismatch sum.
// Self-resets at end of every launch (graph-replay safe).
__device__ unsigned long long g_acc = 0ull;

__global__ void __launch_bounds__(THREADS_, 1)
dsverifier_kernel(const float* __restrict__ c2,
                  const float* __restrict__ c3,
                  const float* __restrict__ mask1,
                  const float* __restrict__ mask2,
                  const float* __restrict__ median1,
                  const float* __restrict__ median2,
                  float* __restrict__ out)
{
    const int tid = threadIdx.x;
    const int bid = blockIdx.x;
    const int i   = bid * THREADS_ + tid;

    bool diff;
    if (bid < BLOCKS1_) {
        float v  = __ldg(&c2[(size_t)i * 4096 + 455]);
        float mk = __ldg(&mask1[i]);
        float md = __ldg(median1);
        diff = (v > md) != (mk != 0.0f);
    } else {
        const int j = i - N1_;
        float v  = __ldg(&c3[(size_t)j * 1024 + 99]);
        float mk = __ldg(&mask2[j]);
        float md = __ldg(median2);
        diff = (v > md) != (mk != 0.0f);
    }

    const unsigned bal = __ballot_sync(0xFFFFFFFFu, diff);

    if ((tid & 31) == 0) {
        const unsigned cnt = __popc(bal);
        // Single RMW carries both the partial sum and the arrival ticket:
        // no fence, no second atomic, ordering is trivial (same address).
        unsigned long long prev =
            atomicAdd(&g_acc, ((unsigned long long)1 << 32) | (unsigned long long)cnt);
        if ((unsigned)(prev >> 32) == (unsigned)(NWARPS_ - 1)) {
            // Globally last warp: low word already holds all other warps' counts.
            unsigned total = (unsigned)(prev & 0xFFFFFFFFull) + cnt;
            *out = (float)total;                 // exact (<= 38400 < 2^24)
            atomicExch(&g_acc, 0ull);            // reset for next graph replay
        }
    }
}

extern "C" void kernel_launch(void* const* d_in, const int* in_sizes, int n_in,
                              void* d_out, int out_size)
{
    const float* c2      = (const float*)d_in[0];
    const float* c3      = (const float*)d_in[1];
    const float* mask1   = (const float*)d_in[2];
    const float* mask2   = (const float*)d_in[3];
    const float* median1 = (const float*)d_in[4];
    const float* median2 = (const float*)d_in[5];
    float* out = (float*)d_out;

    dsverifier_kernel<<<BLOCKS_, THREADS_>>>(c2, c3, mask1, mask2,
                                             median1, median2, out);
}